// round 2
// baseline (speedup 1.0000x reference)
#include <cuda_runtime.h>
#include <math.h>

// ---------------- problem dims ----------------
#define C2D 32
#define C1D 64
#define TD 2048
#define AVGF 32
#define SEG 64
#define MD 2048            // M = 2048
#define HA 16
#define DH 128
#define NQKV 6144          // 3*M
#define NFF 8192           // 4*M
#define EPS 1e-5f

// ---------------- scratch (static device memory; no allocations) ----------------
__device__ float g_altx[AVGF * MD];
__device__ float g_s[AVGF * MD];
__device__ float g_y[AVGF * MD];
__device__ float g_qkv[AVGF * NQKV];
__device__ float g_imv[AVGF * MD];
__device__ float g_h[AVGF * NFF];
__device__ float g_part[16 * AVGF * NFF];   // max ksplit*32*N partials (16 MB)

// ---------------- helpers ----------------
__device__ __forceinline__ float f4c(const float4& v, int i) {
    switch (i) { case 0: return v.x; case 1: return v.y; case 2: return v.z; default: return v.w; }
}

__device__ __forceinline__ float sinbias(int i, int n) {
    int j2 = n & ~1;  // even column index used in exponent
    // ang = i / 10000^(j2/1024) = i * exp(-j2 * ln(10000)/1024)
    float ang = (float)i * expf(-(float)j2 * (9.210340371976184f / 1024.f));
    return (n & 1) ? cosf(ang) : sinf(ang);
}

// ---------------- segment average:  altx[i][c1*32+c2] = mean_t x[c2][c1][i*64+t] ----------------
__global__ void avg_k(const float* __restrict__ x, float* __restrict__ altx) {
    int idx = blockIdx.x * 256 + threadIdx.x;      // 0..65535
    int i = idx >> 11;
    int m = idx & 2047;
    int c1 = m >> 5;
    int c2 = m & 31;
    const float4* p = (const float4*)(x + ((c2 << 6) + c1) * TD + (i << 6));
    float s = 0.f;
#pragma unroll
    for (int t = 0; t < 16; t++) { float4 v = p[t]; s += v.x + v.y + v.z + v.w; }
    altx[idx] = s * (1.f / 64.f);
}

// ---------------- GEMM: P[ks][i][n] = sum_{m in chunk} A[i][m] * W[n][m] ----------------
// A: [32][K] row-major.  W: [N][K] row-major.  Tile: 32 rows x 128 cols x 64 k.
#define KC 64
#define APITCH 36
#define BPITCH 68

__global__ __launch_bounds__(256) void gemm32_k(
    const float* __restrict__ A, const float* __restrict__ W,
    float* __restrict__ P, int N, int K, int kchunk)
{
    __shared__ __align__(16) float As[KC][APITCH];    // As[k][row]
    __shared__ __align__(16) float Bs[128][BPITCH];   // Bs[col][k]

    int tid = threadIdx.x;
    int colBase = blockIdx.x * 128;
    int kstart = blockIdx.y * kchunk;
    int kend = kstart + kchunk;

    int w = tid >> 5, lane = tid & 31;
    int cl = lane & 3;
    int rg = lane >> 2;
    int r0 = rg * 4;                // this thread's 4 rows: r0..r0+3
    int c0 = w * 16 + cl;           // this thread's 4 cols: c0 + 4*cc

    float acc[4][4];
#pragma unroll
    for (int q = 0; q < 4; q++)
#pragma unroll
        for (int cc = 0; cc < 4; cc++) acc[q][cc] = 0.f;

    int ai = tid >> 3, aj = tid & 7;     // A loader: row ai, float4-col aj(+8)
    int bn = tid >> 4, bj = tid & 15;    // B loader: base row bn, float4-col bj

    for (int k0 = kstart; k0 < kend; k0 += KC) {
        // load A tile 32x64 (transposed into As[k][row])
#pragma unroll
        for (int rep = 0; rep < 2; rep++) {
            int j2 = aj + rep * 8;
            float4 v = *(const float4*)&A[(size_t)ai * K + k0 + j2 * 4];
            As[j2 * 4 + 0][ai] = v.x;
            As[j2 * 4 + 1][ai] = v.y;
            As[j2 * 4 + 2][ai] = v.z;
            As[j2 * 4 + 3][ai] = v.w;
        }
        // load B tile 128x64 (row-major)
#pragma unroll
        for (int p = 0; p < 8; p++) {
            int row = bn + p * 16;
            float4 v = *(const float4*)&W[(size_t)(colBase + row) * K + k0 + bj * 4];
            *(float4*)&Bs[row][bj * 4] = v;
        }
        __syncthreads();

#pragma unroll 4
        for (int kk = 0; kk < KC; kk += 4) {
            float4 bq[4];
#pragma unroll
            for (int cc = 0; cc < 4; cc++)
                bq[cc] = *(const float4*)&Bs[c0 + 4 * cc][kk];
#pragma unroll
            for (int dk = 0; dk < 4; dk++) {
                float4 a = *(const float4*)&As[kk + dk][r0];
#pragma unroll
                for (int q = 0; q < 4; q++) {
                    float av = f4c(a, q);
#pragma unroll
                    for (int cc = 0; cc < 4; cc++)
                        acc[q][cc] += av * f4c(bq[cc], dk);
                }
            }
        }
        __syncthreads();
    }

    float* Pp = P + (size_t)blockIdx.y * 32 * N;
#pragma unroll
    for (int q = 0; q < 4; q++)
#pragma unroll
        for (int cc = 0; cc < 4; cc++)
            Pp[(size_t)(r0 + q) * N + colBase + c0 + 4 * cc] = acc[q][cc];
}

// ---------------- split-K reduce + epilogues ----------------
// mode 0: plain   1: += out (residual)   2: +bias then exact GELU   3: +bias   4: +sinusoidal bias
__global__ void reduce_k(const float* __restrict__ P, float* __restrict__ out,
                         const float* __restrict__ bias, int N, int ks, int mode)
{
    int idx = blockIdx.x * blockDim.x + threadIdx.x;
    int tot = 32 * N;
    if (idx >= tot) return;
    float v = 0.f;
    for (int s = 0; s < ks; s++) v += P[(size_t)s * tot + idx];

    if (mode == 0) {
        out[idx] = v;
    } else if (mode == 1) {
        out[idx] = v + out[idx];
    } else if (mode == 2) {
        int n = idx % N;
        float t = v + bias[n];
        out[idx] = 0.5f * t * (1.f + erff(t * 0.70710678118654752f));
    } else if (mode == 3) {
        int n = idx % N;
        out[idx] = v + bias[n];
    } else { // 4
        out[idx] = v + sinbias(idx >> 11, idx & 2047);
    }
}

// ---------------- LayerNorm (population var), optional +residual ----------------
__global__ void ln_k(const float* __restrict__ in, float* __restrict__ out,
                     const float* __restrict__ g, const float* __restrict__ b, int resid)
{
    int row = blockIdx.x;
    int tid = threadIdx.x;       // 256 threads
    int w = tid >> 5, lane = tid & 31;
    const float* x = in + (size_t)row * MD;
    float vals[8];
    float s = 0.f, s2 = 0.f;
#pragma unroll
    for (int j = 0; j < 8; j++) {
        float v = x[tid + j * 256];
        vals[j] = v; s += v; s2 += v * v;
    }
#pragma unroll
    for (int off = 16; off; off >>= 1) {
        s += __shfl_xor_sync(0xffffffffu, s, off);
        s2 += __shfl_xor_sync(0xffffffffu, s2, off);
    }
    __shared__ float red[64];
    if (lane == 0) { red[w] = s; red[32 + w] = s2; }
    __syncthreads();
    if (tid == 0) {
        float ts = 0.f, t2 = 0.f;
        for (int k = 0; k < 8; k++) { ts += red[k]; t2 += red[32 + k]; }
        red[60] = ts; red[61] = t2;
    }
    __syncthreads();
    float mu = red[60] * (1.f / 2048.f);
    float var = red[61] * (1.f / 2048.f) - mu * mu;
    float rstd = rsqrtf(var + EPS);
#pragma unroll
    for (int j = 0; j < 8; j++) {
        int c = tid + j * 256;
        float nv = (vals[j] - mu) * rstd * g[c] + b[c];
        out[(size_t)row * MD + c] = resid ? (nv + vals[j]) : nv;
    }
}

// ---------------- scalar attention + serial cumsum over tokens ----------------
// rsa[i][h] = (1/sqrt(DH)) * sum_d q[i,h,d]*k[i,h,d];  imv[i,h,d] = cumsum_i rsa*v
__global__ void attn_k(const float* __restrict__ qkv, float* __restrict__ imv) {
    int h = blockIdx.x;                 // 16 heads
    int tid = threadIdx.x;              // 128 threads
    int w = tid >> 5, lane = tid & 31;
    __shared__ float rsa[32];

    // each warp computes rsa for 8 tokens
#pragma unroll
    for (int ii = 0; ii < 8; ii++) {
        int i = w * 8 + ii;
        const float* q = qkv + (size_t)i * NQKV + h * DH;
        const float* k = q + MD;
        float4 qa = *(const float4*)&q[lane * 4];
        float4 ka = *(const float4*)&k[lane * 4];
        float p = qa.x * ka.x + qa.y * ka.y + qa.z * ka.z + qa.w * ka.w;
#pragma unroll
        for (int off = 16; off; off >>= 1) p += __shfl_xor_sync(0xffffffffu, p, off);
        if (lane == 0) rsa[i] = p * 0.08838834764831845f;  // 1/sqrt(128)
    }
    __syncthreads();

    int d = tid;
    float run = 0.f;
    const float* v = qkv + 2 * MD + h * DH + d;
    float* o = imv + h * DH + d;
#pragma unroll
    for (int i = 0; i < 32; i++) {
        run += rsa[i] * v[(size_t)i * NQKV];
        o[(size_t)i * MD] = run;
    }
}

// ---------------- launch ----------------
extern "C" void kernel_launch(void* const* d_in, const int* in_sizes, int n_in,
                              void* d_out, int out_size)
{
    const float* x      = (const float*)d_in[0];
    const float* weight = (const float*)d_in[1];
    const float* Wqkv   = (const float*)d_in[2];
    const float* Wo     = (const float*)d_in[3];
    const float* ln1_g  = (const float*)d_in[4];
    const float* ln1_b  = (const float*)d_in[5];
    const float* ln2_g  = (const float*)d_in[6];
    const float* ln2_b  = (const float*)d_in[7];
    const float* fc1_w  = (const float*)d_in[8];
    const float* fc1_b  = (const float*)d_in[9];
    const float* fc2_w  = (const float*)d_in[10];
    const float* fc2_b  = (const float*)d_in[11];
    float* out = (float*)d_out;

    float *p_altx, *p_s, *p_y, *p_qkv, *p_imv, *p_h, *p_part;
    cudaGetSymbolAddress((void**)&p_altx, g_altx);
    cudaGetSymbolAddress((void**)&p_s,    g_s);
    cudaGetSymbolAddress((void**)&p_y,    g_y);
    cudaGetSymbolAddress((void**)&p_qkv,  g_qkv);
    cudaGetSymbolAddress((void**)&p_imv,  g_imv);
    cudaGetSymbolAddress((void**)&p_h,    g_h);
    cudaGetSymbolAddress((void**)&p_part, g_part);

    // 1) segment average
    avg_k<<<256, 256>>>(x, p_altx);

    // 2) s = altx @ weight^T + sinusoidal bias     (N=2048, K=2048, ksplit=16)
    gemm32_k<<<dim3(16, 16), 256>>>(p_altx, weight, p_part, MD, MD, 128);
    reduce_k<<<256, 256>>>(p_part, p_s, nullptr, MD, 16, 4);

    for (int a = 0; a < 3; a++) {
        // y = LN1(s)
        ln_k<<<32, 256>>>(p_s, p_y, ln1_g, ln1_b, 0);

        // qkv = y @ Wqkv[a]^T   (N=6144, K=2048, ksplit=8)
        gemm32_k<<<dim3(48, 8), 256>>>(p_y, Wqkv + (size_t)a * 3 * HA * DH * MD,
                                       p_part, NQKV, MD, 256);
        reduce_k<<<768, 256>>>(p_part, p_qkv, nullptr, NQKV, 8, 0);

        // scalar attention + cumsum
        attn_k<<<16, 128>>>(p_qkv, p_imv);

        // s = imv @ Wo[a]^T + s   (N=2048, K=2048, ksplit=16)
        gemm32_k<<<dim3(16, 16), 256>>>(p_imv, Wo + (size_t)a * MD * MD,
                                        p_part, MD, MD, 128);
        reduce_k<<<256, 256>>>(p_part, p_s, nullptr, MD, 16, 1);

        // s = LN2(s) + s
        ln_k<<<32, 256>>>(p_s, p_s, ln2_g, ln2_b, 1);

        // h = gelu(s @ fc1^T + b1)   (N=8192, K=2048, ksplit=8)
        gemm32_k<<<dim3(64, 8), 256>>>(p_s, fc1_w, p_part, NFF, MD, 256);
        reduce_k<<<1024, 256>>>(p_part, p_h, fc1_b, NFF, 8, 2);

        // s = h @ fc2^T + b2   (N=2048, K=8192, ksplit=16)
        gemm32_k<<<dim3(16, 16), 256>>>(p_h, fc2_w, p_part, MD, NFF, 512);
        reduce_k<<<256, 256>>>(p_part, (a == 2) ? out : p_s, fc2_b, MD, 16, 3);
    }
}